// round 16
// baseline (speedup 1.0000x reference)
#include <cuda_runtime.h>
#include <cuda_fp16.h>
#include <cstdint>

// Problem constants
#define B_ 4
#define N_ 4096
#define D_ 512
#define K_ 32
#define TILES 32            // N_/128
#define PAIRS 528           // TILES*(TILES+1)/2

#define THRESH 0.09f
#define CAND_MAX 256
#define NROWS (B_ * N_)     // 16384
#define WPR 128             // bitmask words per row (N_/32)

// Scratch (device globals — no runtime allocation allowed)
// g_sim holds only the UPPER tile-triangle (tile_j >= tile_i); lower cells
// are never written nor read.
__device__ __align__(128) __half g_h[(size_t)B_ * N_ * D_];           // 16 MB
__device__ __align__(128) __half g_l[(size_t)B_ * N_ * D_];           // 16 MB
__device__ __align__(128) float g_sim[(size_t)B_ * N_ * N_];          // 268 MB
__device__ __align__(128) uint32_t g_bits[(size_t)NROWS * WPR];       // 8 MB

// ---------------------------------------------------------------------------
// Portable PTX helpers (compute_103-safe)
// ---------------------------------------------------------------------------
__device__ __forceinline__ uint32_t smem_u32(const void* p) {
    uint32_t a;
    asm("{ .reg .u64 t; cvta.to.shared.u64 t, %1; cvt.u32.u64 %0, t; }"
        : "=r"(a) : "l"(p));
    return a;
}

#define SWZ(off) ((off) ^ (((off) >> 3) & 0x70))

#define CP_ASYNC16(dst_u32, src_ptr) \
    asm volatile("cp.async.cg.shared.global [%0], [%1], 16;" \
                 :: "r"(dst_u32), "l"(src_ptr) : "memory")
#define CP_COMMIT() asm volatile("cp.async.commit_group;" ::: "memory")
#define CP_WAIT(n)  asm volatile("cp.async.wait_group %0;" :: "n"(n) : "memory")

#define LDSM_X4(r0, r1, r2, r3, addr) \
    asm volatile("ldmatrix.sync.aligned.m8n8.x4.shared.b16 {%0,%1,%2,%3}, [%4];" \
                 : "=r"(r0), "=r"(r1), "=r"(r2), "=r"(r3) : "r"(addr))

#define MMA16816F16(c, a, b) \
    asm volatile("mma.sync.aligned.m16n8k16.row.col.f32.f16.f16.f32 " \
                 "{%0,%1,%2,%3}, {%4,%5,%6,%7}, {%8,%9}, {%0,%1,%2,%3};" \
                 : "+f"((c)[0]), "+f"((c)[1]), "+f"((c)[2]), "+f"((c)[3]) \
                 : "r"((a)[0]), "r"((a)[1]), "r"((a)[2]), "r"((a)[3]), \
                   "r"((b)[0]), "r"((b)[1]))

// ---------------------------------------------------------------------------
// Kernel 1: row L2-normalization + fp16 2-limb split (unchanged).
// ---------------------------------------------------------------------------
__global__ void __launch_bounds__(128) normalize_kernel(const float* __restrict__ x) {
    int row = blockIdx.x;
    const float* xr = x + (size_t)row * D_;
    int t = threadIdx.x;

    float4 v = ((const float4*)xr)[t];
    float ss = v.x * v.x + v.y * v.y + v.z * v.z + v.w * v.w;
    #pragma unroll
    for (int o = 16; o; o >>= 1) ss += __shfl_xor_sync(0xffffffffu, ss, o);

    __shared__ float wsum[4];
    if ((t & 31) == 0) wsum[t >> 5] = ss;
    __syncthreads();
    float total = wsum[0] + wsum[1] + wsum[2] + wsum[3];
    float scale = 1.0f / fmaxf(sqrtf(total), 1e-12f);

    float xn[4] = {v.x * scale, v.y * scale, v.z * scale, v.w * scale};
    unsigned short hs[4], ls[4];
    #pragma unroll
    for (int q = 0; q < 4; q++) {
        __half h = __float2half_rn(xn[q]);
        float r1 = xn[q] - __half2float(h);
        __half l = __float2half_rn(r1);
        hs[q] = __half_as_ushort(h);
        ls[q] = __half_as_ushort(l);
    }
    uint2 hp, lp;
    hp.x = (uint32_t)hs[0] | ((uint32_t)hs[1] << 16);
    hp.y = (uint32_t)hs[2] | ((uint32_t)hs[3] << 16);
    lp.x = (uint32_t)ls[0] | ((uint32_t)ls[1] << 16);
    lp.y = (uint32_t)ls[2] | ((uint32_t)ls[3] << 16);
    ((uint2*)(g_h + (size_t)row * D_))[t] = hp;
    ((uint2*)(g_l + (size_t)row * D_))[t] = lp;
}

// ---------------------------------------------------------------------------
// Kernel 2: symmetric batched GEMM (EXACT R15 mainloop). Change vs R15:
// the mirror g_sim STORE is removed (upper tile-triangle only); the smem
// transpose is retained solely to compute the mirror-side bitmask.
// ---------------------------------------------------------------------------
#define A_TILE 8192                       // 64 rows x 128B
#define B_TILE 16384                      // 128 rows x 128B
#define BUF_BYTES 49152                   // Ah+Al+Bh+Bl
#define SMEM_TOTAL (2 * BUF_BYTES)        // 98304; transpose (34816B) reuses it

__global__ void __launch_bounds__(256, 2) gemm_hmma_kernel() {
    extern __shared__ __align__(1024) char smem[];
    uint32_t sbase = smem_u32(smem);
    int tid = threadIdx.x;
    int wid = tid >> 5;
    int lane = tid & 31;

    int bidx = blockIdx.x;
    int half = bidx & 1;
    int pp = bidx >> 1;
    int b = pp / PAIRS;
    int u = pp % PAIRS;
    int ti = 0;
    while (u >= TILES - ti) { u -= TILES - ti; ti++; }
    int tj = ti + u;                      // tj >= ti

    size_t aoff = ((size_t)b * N_ + (size_t)ti * 128 + (size_t)half * 64) * D_;
    size_t boff = ((size_t)b * N_ + (size_t)tj * 128) * D_;
    const __half* Ah = g_h + aoff;
    const __half* Al = g_l + aoff;
    const __half* Bh = g_h + boff;
    const __half* Bl = g_l + boff;

    int wm = wid & 1;                     // 2 warps in M (32 rows each)
    int wn = wid >> 1;                    // 4 warps in N (32 cols each)

    float acc[2][4][4];
    #pragma unroll
    for (int mt = 0; mt < 2; mt++)
        #pragma unroll
        for (int nt = 0; nt < 4; nt++)
            #pragma unroll
            for (int q = 0; q < 4; q++) acc[mt][nt][q] = 0.0f;

    auto load_chunk = [&](int kc, int buf) {
        uint32_t base = sbase + buf * BUF_BYTES;
        #pragma unroll
        for (int q = 0; q < 2; ++q) {
            int uu = q * 256 + tid;               // 0..511
            int row = uu >> 3;
            int seg = uu & 7;
            uint32_t sw = SWZ(row * 128 + seg * 16);
            CP_ASYNC16(base + sw, Ah + (size_t)row * D_ + kc * 64 + seg * 8);
            CP_ASYNC16(base + A_TILE + sw, Al + (size_t)row * D_ + kc * 64 + seg * 8);
        }
        #pragma unroll
        for (int q = 0; q < 4; ++q) {
            int uu = q * 256 + tid;               // 0..1023
            int row = uu >> 3;
            int seg = uu & 7;
            uint32_t sw = SWZ(row * 128 + seg * 16);
            CP_ASYNC16(base + 2 * A_TILE + sw, Bh + (size_t)row * D_ + kc * 64 + seg * 8);
            CP_ASYNC16(base + 2 * A_TILE + B_TILE + sw, Bl + (size_t)row * D_ + kc * 64 + seg * 8);
        }
    };

    int lr = lane & 15;
    int lc = (lane >> 4) * 16;

    auto compute_chunk = [&](int buf) {
        uint32_t aHs = sbase + buf * BUF_BYTES;
        uint32_t aLs = aHs + A_TILE;
        uint32_t bHs = aHs + 2 * A_TILE;
        uint32_t bLs = bHs + B_TILE;
        #pragma unroll
        for (int ks = 0; ks < 4; ++ks) {
            int kb = ks * 32;
            uint32_t bh[4][2], bl[4][2];
            #pragma unroll
            for (int h = 0; h < 2; ++h) {
                int row = wn * 32 + h * 16 + lr;
                uint32_t off = SWZ(row * 128 + kb + lc);
                uint32_t r0, r1, r2, r3;
                LDSM_X4(r0, r1, r2, r3, bHs + off);
                bh[2 * h + 0][0] = r0; bh[2 * h + 0][1] = r2;
                bh[2 * h + 1][0] = r1; bh[2 * h + 1][1] = r3;
                LDSM_X4(r0, r1, r2, r3, bLs + off);
                bl[2 * h + 0][0] = r0; bl[2 * h + 0][1] = r2;
                bl[2 * h + 1][0] = r1; bl[2 * h + 1][1] = r3;
            }
            #pragma unroll
            for (int mt = 0; mt < 2; ++mt) {
                int row = wm * 32 + mt * 16 + lr;
                uint32_t off = SWZ(row * 128 + kb + lc);
                uint32_t ah[4], al[4];
                LDSM_X4(ah[0], ah[1], ah[2], ah[3], aHs + off);
                LDSM_X4(al[0], al[1], al[2], al[3], aLs + off);
                #pragma unroll
                for (int nt = 0; nt < 4; ++nt) {
                    MMA16816F16(acc[mt][nt], ah, bh[nt]);   // hh
                    MMA16816F16(acc[mt][nt], ah, bl[nt]);   // hl
                    MMA16816F16(acc[mt][nt], al, bh[nt]);   // lh
                }
            }
        }
    };

    // ---- pipelined main loop over 8 K-chunks ----
    const int NCHUNK = D_ / 64;
    load_chunk(0, 0); CP_COMMIT();
    for (int kc = 0; kc < NCHUNK; ++kc) {
        if (kc + 1 < NCHUNK) {
            load_chunk(kc + 1, (kc + 1) & 1); CP_COMMIT();
            CP_WAIT(1);
        } else {
            CP_WAIT(0);
        }
        __syncthreads();
        compute_chunk(kc & 1);
        __syncthreads();
    }

    // ---- epilogue: direct tile writes (upper tile-triangle only) ----
    float* C = g_sim + (size_t)b * N_ * N_;
    int r0 = ti * 128 + half * 64 + wm * 32 + (lane >> 2);
    int c0 = tj * 128 + wn * 32 + (lane & 3) * 2;
    #pragma unroll
    for (int mt = 0; mt < 2; ++mt)
        #pragma unroll
        for (int nt = 0; nt < 4; ++nt) {
            float2 v01 = make_float2(acc[mt][nt][0], acc[mt][nt][1]);
            float2 v23 = make_float2(acc[mt][nt][2], acc[mt][nt][3]);
            *(float2*)(C + (size_t)(r0 + mt * 16) * N_ + c0 + nt * 8)     = v01;
            *(float2*)(C + (size_t)(r0 + mt * 16 + 8) * N_ + c0 + nt * 8) = v23;
        }

    // ---- row-side bitmask from registers (quad shuffle-OR, plain stores) ----
    #pragma unroll
    for (int mt = 0; mt < 2; ++mt)
        #pragma unroll
        for (int h = 0; h < 2; ++h) {
            uint32_t bw = 0;
            #pragma unroll
            for (int nt = 0; nt < 4; ++nt)
                #pragma unroll
                for (int qq = 0; qq < 2; ++qq)
                    if (acc[mt][nt][2 * h + qq] > THRESH)
                        bw |= 1u << (nt * 8 + (lane & 3) * 2 + qq);
            bw |= __shfl_xor_sync(0xffffffffu, bw, 1);
            bw |= __shfl_xor_sync(0xffffffffu, bw, 2);
            if ((lane & 3) == 0) {
                int grow = b * N_ + ti * 128 + half * 64 + wm * 32 + mt * 16
                         + (lane >> 2) + 8 * h;
                g_bits[(size_t)grow * WPR + tj * 4 + wn] = bw;
            }
        }

    // ---- mirror (off-diag): smem transpose kept ONLY for mirror bitmask ----
    if (ti != tj) {
        float* T = (float*)smem;          // [128][68] floats = 34816 B
        int rl = wm * 32 + (lane >> 2);
        int cl = wn * 32 + (lane & 3) * 2;
        #pragma unroll
        for (int mt = 0; mt < 2; ++mt)
            #pragma unroll
            for (int nt = 0; nt < 4; ++nt) {
                int rr = rl + mt * 16;
                int cc = cl + nt * 8;
                T[(cc + 0) * 68 + rr]     = acc[mt][nt][0];
                T[(cc + 1) * 68 + rr]     = acc[mt][nt][1];
                T[(cc + 0) * 68 + rr + 8] = acc[mt][nt][2];
                T[(cc + 1) * 68 + rr + 8] = acc[mt][nt][3];
            }
        __syncthreads();
        #pragma unroll
        for (int q = 0; q < 8; ++q) {
            int uu = q * 256 + tid;       // 0..2047
            int r = uu >> 4;              // mirror row 0..127 (= original col)
            int c4 = uu & 15;             // float4 index (= lane & 15)
            float4 v = *(float4*)&T[r * 68 + c4 * 4];

            // bitmask: 8-thread group covers one 32-col word (NO g_sim store)
            uint32_t nib = (v.x > THRESH ? 1u : 0u) | (v.y > THRESH ? 2u : 0u)
                         | (v.z > THRESH ? 4u : 0u) | (v.w > THRESH ? 8u : 0u);
            uint32_t w = nib << ((c4 & 7) * 4);
            w |= __shfl_xor_sync(0xffffffffu, w, 1);
            w |= __shfl_xor_sync(0xffffffffu, w, 2);
            w |= __shfl_xor_sync(0xffffffffu, w, 4);
            if ((lane & 7) == 0) {
                int grow = b * N_ + tj * 128 + r;
                g_bits[(size_t)grow * WPR + ti * 4 + half * 2 + (c4 >> 3)] = w;
            }
        }
    }
}

// ---------------------------------------------------------------------------
// Kernel 3: bitmask-driven candidate gather + exact top-32 + scatter.
// g_sim holds only the upper tile-triangle: a candidate j of row i reads
// sim[i][j] if (j>>7) >= (i>>7), else sim[j][i] (bitwise the same value the
// mirror copy used to provide).
// ---------------------------------------------------------------------------
__global__ void __launch_bounds__(256) topk_scatter_kernel(float* __restrict__ out) {
    int row = blockIdx.x;
    int b = row >> 12;
    int i = row & (N_ - 1);
    const float* base = g_sim + (size_t)b * N_ * N_;
    int t = threadIdx.x;
    int lane = t & 31, warp = t >> 5;
    int itile = i >> 7;

    const float NEG_INF = __int_as_float(0xff800000);

    __shared__ float cV[CAND_MAX];
    __shared__ int   cI[CAND_MAX];
    __shared__ int   scnt;
    __shared__ float sV[K_];
    __shared__ int   sI[K_];
    if (t == 0) scnt = 0;
    __syncthreads();

    // ---- candidate extraction from bitmask (t < 128: one word each) ----
    if (t < WPR) {
        uint32_t w = g_bits[(size_t)row * WPR + t];
        if (w) {
            int n = __popc(w);
            int bpos = atomicAdd(&scnt, n);
            while (w) {
                int bp = __ffs(w) - 1;
                w &= w - 1;
                if (bpos < CAND_MAX) {
                    int j = t * 32 + bp;
                    float v = ((j >> 7) < itile) ? base[(size_t)j * N_ + i]
                                                 : base[(size_t)i * N_ + j];
                    cV[bpos] = v;
                    cI[bpos] = j;
                }
                bpos++;
            }
        }
    }
    __syncthreads();
    int cnt = scnt;

    if (cnt >= K_ && cnt <= CAND_MAX) {
        if (warp == 0) {
            float cv[8]; int ci[8];
            #pragma unroll
            for (int j = 0; j < 8; j++) {
                int idx = j * 32 + lane;
                bool ok = idx < cnt;
                cv[j] = ok ? cV[idx] : NEG_INF;
                ci[j] = ok ? cI[idx] : 0x7fffffff;
            }
            for (int r = 0; r < K_; r++) {
                float bv = cv[0]; int bi = ci[0];
                #pragma unroll
                for (int j = 1; j < 8; j++)
                    if (cv[j] > bv || (cv[j] == bv && ci[j] < bi)) { bv = cv[j]; bi = ci[j]; }
                #pragma unroll
                for (int o = 16; o; o >>= 1) {
                    float ov = __shfl_xor_sync(0xffffffffu, bv, o);
                    int   oi = __shfl_xor_sync(0xffffffffu, bi, o);
                    if (ov > bv || (ov == bv && oi < bi)) { bv = ov; bi = oi; }
                }
                if (lane == 0) { sV[r] = bv; sI[r] = bi; }
                #pragma unroll
                for (int j = 0; j < 8; j++)
                    if (ci[j] == bi) cv[j] = NEG_INF;
            }
        }
    } else {
        // ---- fallback: full-row exact top-32 with triangle addressing ----
        float v[16];
        #pragma unroll
        for (int q = 0; q < 16; q++) {
            int j = warp * 512 + q * 32 + lane;
            v[q] = ((j >> 7) < itile) ? base[(size_t)j * N_ + i]
                                      : base[(size_t)i * N_ + j];
        }

        for (int r = 0; r < K_; r++) {
            float bv = v[0]; int bq = 0;
            #pragma unroll
            for (int q = 1; q < 16; q++)
                if (v[q] > bv) { bv = v[q]; bq = q; }
            int bix = warp * 512 + bq * 32 + lane;

            #pragma unroll
            for (int o = 16; o; o >>= 1) {
                float ov = __shfl_xor_sync(0xffffffffu, bv, o);
                int   oi = __shfl_xor_sync(0xffffffffu, bix, o);
                if (ov > bv || (ov == bv && oi < bix)) { bv = ov; bix = oi; }
            }
            if (lane == 0) { cV[warp * 32 + r] = bv; cI[warp * 32 + r] = bix; }
            if ((bix & 31) == lane) v[(bix >> 5) & 15] = NEG_INF;
            __syncwarp();
        }
        __syncthreads();
        if (warp == 0) {
            float cv[8]; int ci[8];
            #pragma unroll
            for (int j = 0; j < 8; j++) { cv[j] = cV[j * 32 + lane]; ci[j] = cI[j * 32 + lane]; }
            for (int r = 0; r < K_; r++) {
                float bv = cv[0]; int bi = ci[0];
                #pragma unroll
                for (int j = 1; j < 8; j++)
                    if (cv[j] > bv || (cv[j] == bv && ci[j] < bi)) { bv = cv[j]; bi = ci[j]; }
                #pragma unroll
                for (int o = 16; o; o >>= 1) {
                    float ov = __shfl_xor_sync(0xffffffffu, bv, o);
                    int   oi = __shfl_xor_sync(0xffffffffu, bi, o);
                    if (ov > bv || (ov == bv && oi < bi)) { bv = ov; bi = oi; }
                }
                if (lane == 0) { sV[r] = bv; sI[r] = bi; }
                #pragma unroll
                for (int j = 0; j < 8; j++)
                    if (ci[j] == bi) cv[j] = NEG_INF;
            }
        }
    }
    __syncthreads();

    if (t < K_) {
        float val = 0.5f * sV[t];
        int j = sI[t];
        float* ob = out + (size_t)b * N_ * N_;
        atomicAdd(ob + (size_t)i * N_ + j, val);
        atomicAdd(ob + (size_t)j * N_ + i, val);
    }
}

// ---------------------------------------------------------------------------
// Launcher: serial form (measured best).
// ---------------------------------------------------------------------------
extern "C" void kernel_launch(void* const* d_in, const int* in_sizes, int n_in,
                              void* d_out, int out_size) {
    const float* x = (const float*)d_in[0];
    float* out = (float*)d_out;

    cudaFuncSetAttribute(gemm_hmma_kernel,
                         cudaFuncAttributeMaxDynamicSharedMemorySize, SMEM_TOTAL);

    cudaMemsetAsync(out, 0, (size_t)out_size * sizeof(float));
    normalize_kernel<<<B_ * N_, 128>>>(x);
    gemm_hmma_kernel<<<B_ * PAIRS * 2, 256, SMEM_TOTAL>>>();
    topk_scatter_kernel<<<B_ * N_, 256>>>(out);
}

// round 17
// speedup vs baseline: 1.0894x; 1.0894x over previous
#include <cuda_runtime.h>
#include <cuda_fp16.h>
#include <cstdint>

// Problem constants
#define B_ 4
#define N_ 4096
#define D_ 512
#define K_ 32
#define TILES 32            // N_/128
#define PAIRS 528           // TILES*(TILES+1)/2

#define THRESH 0.09f
#define CAND_MAX 256
#define NROWS (B_ * N_)     // 16384
#define WPR 128             // bitmask words per row (N_/32)

// Scratch (device globals — no runtime allocation allowed)
__device__ __align__(128) __half g_h[(size_t)B_ * N_ * D_];           // 16 MB
__device__ __align__(128) __half g_l[(size_t)B_ * N_ * D_];           // 16 MB
__device__ __align__(128) float g_sim[(size_t)B_ * N_ * N_];          // 268 MB
__device__ __align__(128) uint32_t g_bits[(size_t)NROWS * WPR];       // 8 MB

// ---------------------------------------------------------------------------
// Portable PTX helpers (compute_103-safe)
// ---------------------------------------------------------------------------
__device__ __forceinline__ uint32_t smem_u32(const void* p) {
    uint32_t a;
    asm("{ .reg .u64 t; cvta.to.shared.u64 t, %1; cvt.u32.u64 %0, t; }"
        : "=r"(a) : "l"(p));
    return a;
}

#define SWZ(off) ((off) ^ (((off) >> 3) & 0x70))

#define CP_ASYNC16(dst_u32, src_ptr) \
    asm volatile("cp.async.cg.shared.global [%0], [%1], 16;" \
                 :: "r"(dst_u32), "l"(src_ptr) : "memory")
#define CP_COMMIT() asm volatile("cp.async.commit_group;" ::: "memory")
#define CP_WAIT(n)  asm volatile("cp.async.wait_group %0;" :: "n"(n) : "memory")

#define LDSM_X4(r0, r1, r2, r3, addr) \
    asm volatile("ldmatrix.sync.aligned.m8n8.x4.shared.b16 {%0,%1,%2,%3}, [%4];" \
                 : "=r"(r0), "=r"(r1), "=r"(r2), "=r"(r3) : "r"(addr))

#define MMA16816F16(c, a, b) \
    asm volatile("mma.sync.aligned.m16n8k16.row.col.f32.f16.f16.f32 " \
                 "{%0,%1,%2,%3}, {%4,%5,%6,%7}, {%8,%9}, {%0,%1,%2,%3};" \
                 : "+f"((c)[0]), "+f"((c)[1]), "+f"((c)[2]), "+f"((c)[3]) \
                 : "r"((a)[0]), "r"((a)[1]), "r"((a)[2]), "r"((a)[3]), \
                   "r"((b)[0]), "r"((b)[1]))

// ---------------------------------------------------------------------------
// Kernel 1: row L2-normalization + fp16 2-limb split (unchanged).
// ---------------------------------------------------------------------------
__global__ void __launch_bounds__(128) normalize_kernel(const float* __restrict__ x) {
    int row = blockIdx.x;
    const float* xr = x + (size_t)row * D_;
    int t = threadIdx.x;

    float4 v = ((const float4*)xr)[t];
    float ss = v.x * v.x + v.y * v.y + v.z * v.z + v.w * v.w;
    #pragma unroll
    for (int o = 16; o; o >>= 1) ss += __shfl_xor_sync(0xffffffffu, ss, o);

    __shared__ float wsum[4];
    if ((t & 31) == 0) wsum[t >> 5] = ss;
    __syncthreads();
    float total = wsum[0] + wsum[1] + wsum[2] + wsum[3];
    float scale = 1.0f / fmaxf(sqrtf(total), 1e-12f);

    float xn[4] = {v.x * scale, v.y * scale, v.z * scale, v.w * scale};
    unsigned short hs[4], ls[4];
    #pragma unroll
    for (int q = 0; q < 4; q++) {
        __half h = __float2half_rn(xn[q]);
        float r1 = xn[q] - __half2float(h);
        __half l = __float2half_rn(r1);
        hs[q] = __half_as_ushort(h);
        ls[q] = __half_as_ushort(l);
    }
    uint2 hp, lp;
    hp.x = (uint32_t)hs[0] | ((uint32_t)hs[1] << 16);
    hp.y = (uint32_t)hs[2] | ((uint32_t)hs[3] << 16);
    lp.x = (uint32_t)ls[0] | ((uint32_t)ls[1] << 16);
    lp.y = (uint32_t)ls[2] | ((uint32_t)ls[3] << 16);
    ((uint2*)(g_h + (size_t)row * D_))[t] = hp;
    ((uint2*)(g_l + (size_t)row * D_))[t] = lp;
}

// ---------------------------------------------------------------------------
// Kernel 2: symmetric batched GEMM (EXACT R15) + overlapped d_out zeroing.
// Each of the first 4096 CTAs zeroes a 64KB slice of d_out with
// fire-and-forget stores issued behind the first cp.async batch; the
// zero-traffic hides in the HMMA-bound mainloop's idle DRAM bandwidth.
// ---------------------------------------------------------------------------
#define A_TILE 8192                       // 64 rows x 128B
#define B_TILE 16384                      // 128 rows x 128B
#define BUF_BYTES 49152                   // Ah+Al+Bh+Bl
#define SMEM_TOTAL (2 * BUF_BYTES)        // 98304; transpose (34816B) reuses it

__global__ void __launch_bounds__(256, 2) gemm_hmma_kernel(float* __restrict__ gout) {
    extern __shared__ __align__(1024) char smem[];
    uint32_t sbase = smem_u32(smem);
    int tid = threadIdx.x;
    int wid = tid >> 5;
    int lane = tid & 31;

    int bidx = blockIdx.x;
    int half = bidx & 1;
    int pp = bidx >> 1;
    int b = pp / PAIRS;
    int u = pp % PAIRS;
    int ti = 0;
    while (u >= TILES - ti) { u -= TILES - ti; ti++; }
    int tj = ti + u;                      // tj >= ti

    size_t aoff = ((size_t)b * N_ + (size_t)ti * 128 + (size_t)half * 64) * D_;
    size_t boff = ((size_t)b * N_ + (size_t)tj * 128) * D_;
    const __half* Ah = g_h + aoff;
    const __half* Al = g_l + aoff;
    const __half* Bh = g_h + boff;
    const __half* Bl = g_l + boff;

    int wm = wid & 1;                     // 2 warps in M (32 rows each)
    int wn = wid >> 1;                    // 4 warps in N (32 cols each)

    float acc[2][4][4];
    #pragma unroll
    for (int mt = 0; mt < 2; mt++)
        #pragma unroll
        for (int nt = 0; nt < 4; nt++)
            #pragma unroll
            for (int q = 0; q < 4; q++) acc[mt][nt][q] = 0.0f;

    auto load_chunk = [&](int kc, int buf) {
        uint32_t base = sbase + buf * BUF_BYTES;
        #pragma unroll
        for (int q = 0; q < 2; ++q) {
            int uu = q * 256 + tid;               // 0..511
            int row = uu >> 3;
            int seg = uu & 7;
            uint32_t sw = SWZ(row * 128 + seg * 16);
            CP_ASYNC16(base + sw, Ah + (size_t)row * D_ + kc * 64 + seg * 8);
            CP_ASYNC16(base + A_TILE + sw, Al + (size_t)row * D_ + kc * 64 + seg * 8);
        }
        #pragma unroll
        for (int q = 0; q < 4; ++q) {
            int uu = q * 256 + tid;               // 0..1023
            int row = uu >> 3;
            int seg = uu & 7;
            uint32_t sw = SWZ(row * 128 + seg * 16);
            CP_ASYNC16(base + 2 * A_TILE + sw, Bh + (size_t)row * D_ + kc * 64 + seg * 8);
            CP_ASYNC16(base + 2 * A_TILE + B_TILE + sw, Bl + (size_t)row * D_ + kc * 64 + seg * 8);
        }
    };

    int lr = lane & 15;
    int lc = (lane >> 4) * 16;

    auto compute_chunk = [&](int buf) {
        uint32_t aHs = sbase + buf * BUF_BYTES;
        uint32_t aLs = aHs + A_TILE;
        uint32_t bHs = aHs + 2 * A_TILE;
        uint32_t bLs = bHs + B_TILE;
        #pragma unroll
        for (int ks = 0; ks < 4; ++ks) {
            int kb = ks * 32;
            uint32_t bh[4][2], bl[4][2];
            #pragma unroll
            for (int h = 0; h < 2; ++h) {
                int row = wn * 32 + h * 16 + lr;
                uint32_t off = SWZ(row * 128 + kb + lc);
                uint32_t r0, r1, r2, r3;
                LDSM_X4(r0, r1, r2, r3, bHs + off);
                bh[2 * h + 0][0] = r0; bh[2 * h + 0][1] = r2;
                bh[2 * h + 1][0] = r1; bh[2 * h + 1][1] = r3;
                LDSM_X4(r0, r1, r2, r3, bLs + off);
                bl[2 * h + 0][0] = r0; bl[2 * h + 0][1] = r2;
                bl[2 * h + 1][0] = r1; bl[2 * h + 1][1] = r3;
            }
            #pragma unroll
            for (int mt = 0; mt < 2; ++mt) {
                int row = wm * 32 + mt * 16 + lr;
                uint32_t off = SWZ(row * 128 + kb + lc);
                uint32_t ah[4], al[4];
                LDSM_X4(ah[0], ah[1], ah[2], ah[3], aHs + off);
                LDSM_X4(al[0], al[1], al[2], al[3], aLs + off);
                #pragma unroll
                for (int nt = 0; nt < 4; ++nt) {
                    MMA16816F16(acc[mt][nt], ah, bh[nt]);   // hh
                    MMA16816F16(acc[mt][nt], ah, bl[nt]);   // hl
                    MMA16816F16(acc[mt][nt], al, bh[nt]);   // lh
                }
            }
        }
    };

    // ---- pipelined main loop over 8 K-chunks ----
    const int NCHUNK = D_ / 64;
    load_chunk(0, 0); CP_COMMIT();

    // ---- overlapped d_out zeroing: 4096 CTAs x 16384 floats = full output.
    // Plain stores, no dependence; they drain while the mainloop runs.
    if (bidx < 4096) {
        float4* dst = (float4*)(gout + (size_t)bidx * 16384);
        float4 z = make_float4(0.f, 0.f, 0.f, 0.f);
        #pragma unroll
        for (int q = 0; q < 16; ++q)
            dst[q * 256 + tid] = z;
    }

    for (int kc = 0; kc < NCHUNK; ++kc) {
        if (kc + 1 < NCHUNK) {
            load_chunk(kc + 1, (kc + 1) & 1); CP_COMMIT();
            CP_WAIT(1);
        } else {
            CP_WAIT(0);
        }
        __syncthreads();
        compute_chunk(kc & 1);
        __syncthreads();
    }

    // ---- epilogue: direct tile writes ----
    float* C = g_sim + (size_t)b * N_ * N_;
    int r0 = ti * 128 + half * 64 + wm * 32 + (lane >> 2);
    int c0 = tj * 128 + wn * 32 + (lane & 3) * 2;
    #pragma unroll
    for (int mt = 0; mt < 2; ++mt)
        #pragma unroll
        for (int nt = 0; nt < 4; ++nt) {
            float2 v01 = make_float2(acc[mt][nt][0], acc[mt][nt][1]);
            float2 v23 = make_float2(acc[mt][nt][2], acc[mt][nt][3]);
            *(float2*)(C + (size_t)(r0 + mt * 16) * N_ + c0 + nt * 8)     = v01;
            *(float2*)(C + (size_t)(r0 + mt * 16 + 8) * N_ + c0 + nt * 8) = v23;
        }

    // ---- row-side bitmask from registers (quad shuffle-OR, plain stores) ----
    #pragma unroll
    for (int mt = 0; mt < 2; ++mt)
        #pragma unroll
        for (int h = 0; h < 2; ++h) {
            uint32_t bw = 0;
            #pragma unroll
            for (int nt = 0; nt < 4; ++nt)
                #pragma unroll
                for (int qq = 0; qq < 2; ++qq)
                    if (acc[mt][nt][2 * h + qq] > THRESH)
                        bw |= 1u << (nt * 8 + (lane & 3) * 2 + qq);
            bw |= __shfl_xor_sync(0xffffffffu, bw, 1);
            bw |= __shfl_xor_sync(0xffffffffu, bw, 2);
            if ((lane & 3) == 0) {
                int grow = b * N_ + ti * 128 + half * 64 + wm * 32 + mt * 16
                         + (lane >> 2) + 8 * h;
                g_bits[(size_t)grow * WPR + tj * 4 + wn] = bw;
            }
        }

    // ---- mirror (off-diag): transpose + g_sim write + mirror bitmask ----
    if (ti != tj) {
        float* T = (float*)smem;          // [128][68] floats = 34816 B
        int rl = wm * 32 + (lane >> 2);
        int cl = wn * 32 + (lane & 3) * 2;
        #pragma unroll
        for (int mt = 0; mt < 2; ++mt)
            #pragma unroll
            for (int nt = 0; nt < 4; ++nt) {
                int rr = rl + mt * 16;
                int cc = cl + nt * 8;
                T[(cc + 0) * 68 + rr]     = acc[mt][nt][0];
                T[(cc + 1) * 68 + rr]     = acc[mt][nt][1];
                T[(cc + 0) * 68 + rr + 8] = acc[mt][nt][2];
                T[(cc + 1) * 68 + rr + 8] = acc[mt][nt][3];
            }
        __syncthreads();
        int jb = tj * 128, ib = ti * 128 + half * 64;
        #pragma unroll
        for (int q = 0; q < 8; ++q) {
            int uu = q * 256 + tid;       // 0..2047
            int r = uu >> 4;              // mirror row 0..127 (= original col)
            int c4 = uu & 15;             // float4 index (= lane & 15)
            float4 v = *(float4*)&T[r * 68 + c4 * 4];
            *(float4*)(C + (size_t)(jb + r) * N_ + ib + c4 * 4) = v;

            // bitmask: 8-thread group covers one 32-col word
            uint32_t nib = (v.x > THRESH ? 1u : 0u) | (v.y > THRESH ? 2u : 0u)
                         | (v.z > THRESH ? 4u : 0u) | (v.w > THRESH ? 8u : 0u);
            uint32_t w = nib << ((c4 & 7) * 4);
            w |= __shfl_xor_sync(0xffffffffu, w, 1);
            w |= __shfl_xor_sync(0xffffffffu, w, 2);
            w |= __shfl_xor_sync(0xffffffffu, w, 4);
            if ((lane & 7) == 0) {
                int grow = b * N_ + tj * 128 + r;
                g_bits[(size_t)grow * WPR + ti * 4 + half * 2 + (c4 >> 3)] = w;
            }
        }
    }
}

// ---------------------------------------------------------------------------
// Kernel 3: bitmask-driven candidate gather + exact top-32 + scatter
// (EXACT R15).
// ---------------------------------------------------------------------------
__global__ void __launch_bounds__(256) topk_scatter_kernel(float* __restrict__ out) {
    int row = blockIdx.x;
    int b = row >> 12;
    int i = row & (N_ - 1);
    const float* srow = g_sim + (size_t)b * N_ * N_ + (size_t)i * N_;
    int t = threadIdx.x;
    int lane = t & 31, warp = t >> 5;

    const float NEG_INF = __int_as_float(0xff800000);

    __shared__ float cV[CAND_MAX];
    __shared__ int   cI[CAND_MAX];
    __shared__ int   scnt;
    __shared__ float sV[K_];
    __shared__ int   sI[K_];
    if (t == 0) scnt = 0;
    __syncthreads();

    // ---- candidate extraction from bitmask (t < 128: one word each) ----
    if (t < WPR) {
        uint32_t w = g_bits[(size_t)row * WPR + t];
        if (w) {
            int n = __popc(w);
            int base = atomicAdd(&scnt, n);
            while (w) {
                int bp = __ffs(w) - 1;
                w &= w - 1;
                if (base < CAND_MAX) {
                    int j = t * 32 + bp;
                    cV[base] = srow[j];
                    cI[base] = j;
                }
                base++;
            }
        }
    }
    __syncthreads();
    int cnt = scnt;

    if (cnt >= K_ && cnt <= CAND_MAX) {
        if (warp == 0) {
            float cv[8]; int ci[8];
            #pragma unroll
            for (int j = 0; j < 8; j++) {
                int idx = j * 32 + lane;
                bool ok = idx < cnt;
                cv[j] = ok ? cV[idx] : NEG_INF;
                ci[j] = ok ? cI[idx] : 0x7fffffff;
            }
            for (int r = 0; r < K_; r++) {
                float bv = cv[0]; int bi = ci[0];
                #pragma unroll
                for (int j = 1; j < 8; j++)
                    if (cv[j] > bv || (cv[j] == bv && ci[j] < bi)) { bv = cv[j]; bi = ci[j]; }
                #pragma unroll
                for (int o = 16; o; o >>= 1) {
                    float ov = __shfl_xor_sync(0xffffffffu, bv, o);
                    int   oi = __shfl_xor_sync(0xffffffffu, bi, o);
                    if (ov > bv || (ov == bv && oi < bi)) { bv = ov; bi = oi; }
                }
                if (lane == 0) { sV[r] = bv; sI[r] = bi; }
                #pragma unroll
                for (int j = 0; j < 8; j++)
                    if (ci[j] == bi) cv[j] = NEG_INF;
            }
        }
    } else {
        // ---- fallback: full-row exact top-32 (R12 method; ~never taken) ----
        float v[16];
        #pragma unroll
        for (int q = 0; q < 16; q++) v[q] = srow[warp * 512 + q * 32 + lane];

        for (int r = 0; r < K_; r++) {
            float bv = v[0]; int bq = 0;
            #pragma unroll
            for (int q = 1; q < 16; q++)
                if (v[q] > bv) { bv = v[q]; bq = q; }
            int bix = warp * 512 + bq * 32 + lane;

            #pragma unroll
            for (int o = 16; o; o >>= 1) {
                float ov = __shfl_xor_sync(0xffffffffu, bv, o);
                int   oi = __shfl_xor_sync(0xffffffffu, bix, o);
                if (ov > bv || (ov == bv && oi < bix)) { bv = ov; bix = oi; }
            }
            if (lane == 0) { cV[warp * 32 + r] = bv; cI[warp * 32 + r] = bix; }
            if ((bix & 31) == lane) v[(bix >> 5) & 15] = NEG_INF;
            __syncwarp();
        }
        __syncthreads();
        if (warp == 0) {
            float cv[8]; int ci[8];
            #pragma unroll
            for (int j = 0; j < 8; j++) { cv[j] = cV[j * 32 + lane]; ci[j] = cI[j * 32 + lane]; }
            for (int r = 0; r < K_; r++) {
                float bv = cv[0]; int bi = ci[0];
                #pragma unroll
                for (int j = 1; j < 8; j++)
                    if (cv[j] > bv || (cv[j] == bv && ci[j] < bi)) { bv = cv[j]; bi = ci[j]; }
                #pragma unroll
                for (int o = 16; o; o >>= 1) {
                    float ov = __shfl_xor_sync(0xffffffffu, bv, o);
                    int   oi = __shfl_xor_sync(0xffffffffu, bi, o);
                    if (ov > bv || (ov == bv && oi < bi)) { bv = ov; bi = oi; }
                }
                if (lane == 0) { sV[r] = bv; sI[r] = bi; }
                #pragma unroll
                for (int j = 0; j < 8; j++)
                    if (ci[j] == bi) cv[j] = NEG_INF;
            }
        }
    }
    __syncthreads();

    if (t < K_) {
        float val = 0.5f * sV[t];
        int j = sI[t];
        float* ob = out + (size_t)b * N_ * N_;
        atomicAdd(ob + (size_t)i * N_ + j, val);
        atomicAdd(ob + (size_t)j * N_ + i, val);
    }
}

// ---------------------------------------------------------------------------
// Launcher: memset removed — d_out zeroing happens inside the GEMM, fully
// overlapped with the HMMA-bound mainloop.
// ---------------------------------------------------------------------------
extern "C" void kernel_launch(void* const* d_in, const int* in_sizes, int n_in,
                              void* d_out, int out_size) {
    const float* x = (const float*)d_in[0];
    float* out = (float*)d_out;

    cudaFuncSetAttribute(gemm_hmma_kernel,
                         cudaFuncAttributeMaxDynamicSharedMemorySize, SMEM_TOTAL);

    normalize_kernel<<<B_ * N_, 128>>>(x);
    gemm_hmma_kernel<<<B_ * PAIRS * 2, 256, SMEM_TOTAL>>>(out);
    topk_scatter_kernel<<<B_ * N_, 256>>>(out);
}